// round 4
// baseline (speedup 1.0000x reference)
#include <cuda_runtime.h>

typedef unsigned long long ull;

#define T_LEN 512
#define NB    32          // batch rows per CTA
#define NTH   256
#define HSTR  33          // h state row stride (words), layout [k][r]
#define XSTR  32          // x tile row stride,        layout [t][r]
#define GCOLS 224         // padded gate columns: col = 4*u + g, u<56

// ---- shared memory layout (float offsets) ----
#define OFF_WT1 0                         // [100][224]: k<50 Wih1^T, k>=50 Whh1^T (prescaled)
#define OFF_WT0 (OFF_WT1 + 100*GCOLS)    // [50][224]:  Whh0^T (prescaled)
#define OFF_WX0 (OFF_WT0 + 50*GCOLS)     // [224]: Wih0 column (prescaled)
#define OFF_B0  (OFF_WX0 + GCOLS)        // [224]: (b_ih0+b_hh0) prescaled
#define OFF_B1  (OFF_B0  + GCOLS)        // [224]
#define OFF_XS  (OFF_B1  + GCOLS)        // [513][32] (row 512 = zeros)
#define OFF_H0  (OFF_XS  + 513*XSTR)     // [2][50*33] double-buffered
#define OFF_H1  (OFF_H0  + 2*50*HSTR)    // [2][50*33]
#define OFF_FC  (OFF_H1  + 2*50*HSTR)    // [56]
#define SMEMF   (OFF_FC  + 56)           // 57344 floats = 229376 B

#define SCALE_S (-1.4426950408889634f)   // sigmoid gates: sig(x)=rcp(1+ex2(-x*log2e))
#define SCALE_T (-2.8853900817779268f)   // tanh:          tanh(x)=2*rcp(1+ex2(-2x*log2e))-1

// ---- packed f32x2 + MUFU helpers ----
__device__ __forceinline__ ull pack2(float x, float y) {
    ull r; asm("mov.b64 %0, {%1, %2};" : "=l"(r) : "f"(x), "f"(y)); return r;
}
__device__ __forceinline__ void unpack2(ull v, float& x, float& y) {
    asm("mov.b64 {%0, %1}, %2;" : "=f"(x), "=f"(y) : "l"(v));
}
__device__ __forceinline__ void fma2(ull& d, ull a, ull b) {
    asm("fma.rn.f32x2 %0, %1, %2, %0;" : "+l"(d) : "l"(a), "l"(b));
}
__device__ __forceinline__ float fex2(float x) {
    float r; asm("ex2.approx.f32 %0, %1;" : "=f"(r) : "f"(x)); return r;
}
__device__ __forceinline__ float frcp(float x) {
    float r; asm("rcp.approx.f32 %0, %1;" : "=f"(r) : "f"(x)); return r;
}
#define BARH(id) asm volatile("bar.sync %0, 128;" :: "r"(id) : "memory")

// one k step: 28 gate cols (14 f32x2 accumulators) += h * w[28]
__device__ __forceinline__ void mvk(ull* a, ull h2, const float* w) {
    const ulonglong2* w2 = reinterpret_cast<const ulonglong2*>(w);
    #pragma unroll
    for (int q = 0; q < 7; ++q) {
        ulonglong2 v = w2[q];          // LDS.128, conflict-free
        fma2(a[2*q],     h2, v.x);
        fma2(a[2*q + 1], h2, v.y);
    }
}
__device__ __forceinline__ void initb(ull* a, const float* b) {
    const ulonglong2* b2 = reinterpret_cast<const ulonglong2*>(b);
    #pragma unroll
    for (int q = 0; q < 7; ++q) { ulonglong2 v = b2[q]; a[2*q] = v.x; a[2*q+1] = v.y; }
}
__device__ __forceinline__ void initbx(ull* a, const float* b, const float* wx, ull x2) {
    initb(a, b);
    mvk(a, x2, wx);
}

// LSTM cell update for 7 units; gate pre-acts already scaled (i/f/o: -log2e, g: -2log2e)
__device__ __forceinline__ void actup(const ull* a, float* c, float* hdst, int ubase, int r) {
    #pragma unroll
    for (int j = 0; j < 7; ++j) {
        float gi, gf, gg, go;
        unpack2(a[2*j],     gi, gf);
        unpack2(a[2*j + 1], gg, go);
        float si = frcp(1.f + fex2(gi));
        float sf = frcp(1.f + fex2(gf));
        float sg = frcp(1.f + fex2(gg));
        float so = frcp(1.f + fex2(go));
        float tg = fmaf(2.f, sg, -1.f);
        float cn = fmaf(sf, c[j], si * tg);
        c[j] = cn;
        float tc = fmaf(2.f, frcp(1.f + fex2(SCALE_T * cn)), -1.f);
        if (ubase + j < 50) hdst[(ubase + j)*HSTR + r] = so * tc;
    }
}

__global__ void __launch_bounds__(NTH, 1)
lstm_v2_kernel(const float* __restrict__ x,
               const float* __restrict__ Wih0, const float* __restrict__ Whh0,
               const float* __restrict__ bih0, const float* __restrict__ bhh0,
               const float* __restrict__ Wih1, const float* __restrict__ Whh1,
               const float* __restrict__ bih1, const float* __restrict__ bhh1,
               const float* __restrict__ fcw_g, const float* __restrict__ fcb_g,
               float* __restrict__ out)
{
    extern __shared__ float sm[];
    float* wt1 = sm + OFF_WT1;
    float* wt0 = sm + OFF_WT0;
    float* wx0 = sm + OFF_WX0;
    float* bs0 = sm + OFF_B0;
    float* bs1 = sm + OFF_B1;
    float* xs  = sm + OFF_XS;
    float* h0  = sm + OFF_H0;
    float* h1  = sm + OFF_H1;
    float* fcs = sm + OFF_FC;

    const int tid = threadIdx.x;
    const int b0  = blockIdx.x * NB;

    // ---------------- staging ----------------
    for (int idx = tid; idx < 100*GCOLS; idx += NTH) {
        int k = idx / GCOLS, col = idx - k*GCOLS;
        int u = col >> 2, g = col & 3;
        float s = (g == 2) ? SCALE_T : SCALE_S;
        float v = 0.f;
        if (u < 50) {
            int row = g*50 + u;
            v = (k < 50) ? Wih1[row*50 + k] : Whh1[row*50 + (k - 50)];
        }
        wt1[idx] = v * s;
    }
    for (int idx = tid; idx < 50*GCOLS; idx += NTH) {
        int k = idx / GCOLS, col = idx - k*GCOLS;
        int u = col >> 2, g = col & 3;
        float s = (g == 2) ? SCALE_T : SCALE_S;
        float v = (u < 50) ? Whh0[(g*50 + u)*50 + k] : 0.f;
        wt0[idx] = v * s;
    }
    if (tid < GCOLS) {
        int u = tid >> 2, g = tid & 3;
        float s = (g == 2) ? SCALE_T : SCALE_S;
        int row = g*50 + u;
        wx0[tid] = (u < 50) ? Wih0[row] * s : 0.f;
        bs0[tid] = (u < 50) ? (bih0[row] + bhh0[row]) * s : 0.f;
        bs1[tid] = (u < 50) ? (bih1[row] + bhh1[row]) * s : 0.f;
    }
    if (tid < 50) fcs[tid] = fcw_g[tid];
    for (int idx = tid; idx < NB*T_LEN; idx += NTH) {
        int r = idx >> 9, t = idx & (T_LEN - 1);
        xs[t*XSTR + r] = x[(size_t)(b0 + r)*T_LEN + t];   // coalesced global read
    }
    if (tid < XSTR) xs[512*XSTR + tid] = 0.f;             // zero row for t=511's lookahead
    for (int idx = tid; idx < 2*50*HSTR; idx += NTH) { h0[idx] = 0.f; h1[idx] = 0.f; }
    __syncthreads();

    // ---------------- per-thread geometry ----------------
    const int half = tid >> 7;                // 0: rows 0-15 (warps 0-3), 1: rows 16-31
    const int lt   = tid & 127;
    const int c    = lt >> 4;                 // chunk 0..7 (28 gate cols each)
    const int r    = half*16 + (lt & 15);     // batch row 0..31
    const int co   = 28 * c;                  // column offset
    const int ub   = 7 * c;                   // first unit of this chunk

    const float* wt1c = wt1 + co;
    const float* wt0c = wt0 + co;
    const float* wx0c = wx0 + co;
    const float* b0c  = bs0 + co;
    const float* b1c  = bs1 + co;

    // one-time skew for half 0: anti-align the halves so one half's MUFU act
    // phase overlaps the other half's FFMA2 matvec phase
    if (half == 0) {
        float d = 1.0f + (float)(tid & 31) * 1e-7f;
        #pragma unroll 8
        for (int i = 0; i < 256; ++i) d = fmaf(d, 1.0000001f, 1e-12f);
        if (d == -3.0f) ((volatile float*)sm)[OFF_FC + 55] = d;   // never taken; keeps chain
    }

    float c0r[7], c1r[7];
    #pragma unroll
    for (int j = 0; j < 7; ++j) { c0r[j] = 0.f; c1r[j] = 0.f; }

    // ---------------- prologue: h0(0) from x(0) only (h(-1)=0) ----------------
    {
        ull acc0[14];
        float xv = xs[0*XSTR + r];
        initbx(acc0, b0c, wx0c, pack2(xv, xv));
        actup(acc0, c0r, h0 + 0*50*HSTR, ub, r);   // h0(0) -> buf 0
    }
    BARH(1 + half);

    // ---------------- main loop: one barrier per timestep ----------------
    // M(t): acc1 = L1 gates(t) over h0(t),h1(t-1); acc0 = L0 gates(t+1) over h0(t),x(t+1)
    for (int t = 0; t < T_LEN; ++t) {
        const float* h0rd = h0 + (t & 1)*50*HSTR;          // h0(t)
        const float* h1rd = h1 + ((t + 1) & 1)*50*HSTR;    // h1(t-1)
        float* h0wr = h0 + ((t + 1) & 1)*50*HSTR;          // h0(t+1)
        float* h1wr = h1 + (t & 1)*50*HSTR;                // h1(t)

        ull acc1[14], acc0[14];
        initb(acc1, b1c);
        float xv = xs[(t + 1)*XSTR + r];
        initbx(acc0, b0c, wx0c, pack2(xv, xv));

        #pragma unroll 5
        for (int k = 0; k < 50; ++k) {
            float hv = h0rd[k*HSTR + r];
            ull h2 = pack2(hv, hv);
            mvk(acc1, h2, wt1c + k*GCOLS);
            mvk(acc0, h2, wt0c + k*GCOLS);
        }
        // act0 here: its MUFUs drain under the h1-loop's FMA window
        actup(acc0, c0r, h0wr, ub, r);

        #pragma unroll 5
        for (int k = 0; k < 50; ++k) {
            float hv = h1rd[k*HSTR + r];
            mvk(acc1, pack2(hv, hv), wt1c + (50 + k)*GCOLS);
        }
        actup(acc1, c1r, h1wr, ub, r);

        BARH(1 + half);
    }

    // ---------------- final projection ----------------
    __syncthreads();                     // cross-half visibility of h1(511)
    if (tid < NB) {
        const float* hf = h1 + ((T_LEN - 1) & 1)*50*HSTR;  // buf 1
        float s = fcb_g[0];
        #pragma unroll
        for (int u = 0; u < 50; ++u)
            s += fcs[u] * hf[u*HSTR + tid];
        out[b0 + tid] = s;
    }
}

extern "C" void kernel_launch(void* const* d_in, const int* in_sizes, int n_in,
                              void* d_out, int out_size)
{
    const float* x    = (const float*)d_in[0];
    const float* Wih0 = (const float*)d_in[1];
    const float* Whh0 = (const float*)d_in[2];
    const float* bih0 = (const float*)d_in[3];
    const float* bhh0 = (const float*)d_in[4];
    const float* Wih1 = (const float*)d_in[5];
    const float* Whh1 = (const float*)d_in[6];
    const float* bih1 = (const float*)d_in[7];
    const float* bhh1 = (const float*)d_in[8];
    const float* fcw  = (const float*)d_in[9];
    const float* fcb  = (const float*)d_in[10];
    float* out = (float*)d_out;

    const int B = in_sizes[0] / T_LEN;            // IN = 1 -> 4096
    const int grid = B / NB;                      // 128 CTAs
    const size_t smem = SMEMF * sizeof(float);    // 229376 B

    cudaFuncSetAttribute(lstm_v2_kernel,
                         cudaFuncAttributeMaxDynamicSharedMemorySize, (int)smem);

    lstm_v2_kernel<<<grid, NTH, smem>>>(
        x, Wih0, Whh0, bih0, bhh0, Wih1, Whh1, bih1, bhh1, fcw, fcb, out);
}

// round 13
// speedup vs baseline: 1.1404x; 1.1404x over previous
#include <cuda_runtime.h>

typedef unsigned long long ull;

#define T_LEN 512
#define NB    32            // batch rows per CTA
#define NTH   256
#define GC    256           // padded gate cols: col = 4*u + g, u < 64 (real u < 50)
#define HSTR  34            // h row stride (even -> 8B-aligned row pairs)

// ---- shared memory layout (float offsets) ----
#define OFF_WT1 0                        // [100][256]: k<50 Wih1^T, k>=50 Whh1^T (prescaled)
#define OFF_WT0 (OFF_WT1 + 100*GC)      // [50][256]: Whh0^T (prescaled)
#define OFF_WX0 (OFF_WT0 + 50*GC)       // [256] Wih0 column (prescaled)
#define OFF_B0  (OFF_WX0 + GC)          // [256]
#define OFF_B1  (OFF_B0  + GC)          // [256]
#define OFF_HB0 (OFF_B1  + GC)          // [50*34] single-buffered h0
#define OFF_HB1 (OFF_HB0 + 50*HSTR)     // [50*34] single-buffered h1
#define OFF_FC  (OFF_HB1 + 50*HSTR)     // [64]
#define SMEMF   (OFF_FC  + 64)          // 42632 floats = 170528 B

#define SCALE_S (-1.4426950408889634f)  // sigmoid gates: sig(x)=rcp(1+ex2(x*-log2e))
#define SCALE_T (-2.8853900817779268f)  // tanh: tanh(x)=2*rcp(1+ex2(x*-2log2e))-1

// ---- packed f32x2 + MUFU helpers ----
__device__ __forceinline__ ull pack2(float x, float y) {
    ull r; asm("mov.b64 %0, {%1, %2};" : "=l"(r) : "f"(x), "f"(y)); return r;
}
__device__ __forceinline__ void unpack2(ull v, float& x, float& y) {
    asm("mov.b64 {%0, %1}, %2;" : "=f"(x), "=f"(y) : "l"(v));
}
__device__ __forceinline__ void fma2(ull& d, ull a, ull b) {
    asm("fma.rn.f32x2 %0, %1, %2, %0;" : "+l"(d) : "l"(a), "l"(b));
}
__device__ __forceinline__ float fex2(float x) {
    float r; asm("ex2.approx.f32 %0, %1;" : "=f"(r) : "f"(x)); return r;
}
__device__ __forceinline__ float frcp(float x) {
    float r; asm("rcp.approx.f32 %0, %1;" : "=f"(r) : "f"(x)); return r;
}

// acc layout: a[0..7] = row0 (8 f32x2 = 16 cols), a[8..15] = row1
__device__ __forceinline__ void mvk2(ull* a, ull ha, ull hb, const float* w) {
    const ulonglong2* w2 = reinterpret_cast<const ulonglong2*>(w);
    #pragma unroll
    for (int q = 0; q < 4; ++q) {
        ulonglong2 v = w2[q];             // LDS.128, 16B line, conflict-free
        fma2(a[2*q],     ha, v.x);
        fma2(a[2*q + 1], ha, v.y);
        fma2(a[8 + 2*q], hb, v.x);
        fma2(a[8 + 2*q + 1], hb, v.y);
    }
}
__device__ __forceinline__ void initb16(ull* a, const float* b) {
    const ulonglong2* b2 = reinterpret_cast<const ulonglong2*>(b);
    #pragma unroll
    for (int q = 0; q < 4; ++q) {
        ulonglong2 v = b2[q];
        a[2*q] = v.x; a[2*q + 1] = v.y;
        a[8 + 2*q] = v.x; a[8 + 2*q + 1] = v.y;
    }
}
__device__ __forceinline__ void hsplat(const float* hp, ull& ha, ull& hb) {
    ull hv = *reinterpret_cast<const ull*>(hp);   // LDS.64 (row pair)
    float x_, y_; unpack2(hv, x_, y_);
    ha = pack2(x_, x_); hb = pack2(y_, y_);
}

// one unit (J in 0..3) LSTM cell update for both rows; gates prescaled
template<int J>
__device__ __forceinline__ void act_unit(const ull* a, float* cs, float* hbase,
                                         int u0, int rp2) {
    float gi0, gf0, gg0, go0, gi1, gf1, gg1, go1;
    unpack2(a[2*J],         gi0, gf0);
    unpack2(a[2*J + 1],     gg0, go0);
    unpack2(a[8 + 2*J],     gi1, gf1);
    unpack2(a[8 + 2*J + 1], gg1, go1);
    float si0 = frcp(1.f + fex2(gi0)), sf0 = frcp(1.f + fex2(gf0));
    float sg0 = frcp(1.f + fex2(gg0)), so0 = frcp(1.f + fex2(go0));
    float si1 = frcp(1.f + fex2(gi1)), sf1 = frcp(1.f + fex2(gf1));
    float sg1 = frcp(1.f + fex2(gg1)), so1 = frcp(1.f + fex2(go1));
    float tg0 = fmaf(2.f, sg0, -1.f),  tg1 = fmaf(2.f, sg1, -1.f);
    float cn0 = fmaf(sf0, cs[2*J],     si0 * tg0);
    float cn1 = fmaf(sf1, cs[2*J + 1], si1 * tg1);
    cs[2*J] = cn0; cs[2*J + 1] = cn1;
    float h0v = so0 * fmaf(2.f, frcp(1.f + fex2(SCALE_T * cn0)), -1.f);
    float h1v = so1 * fmaf(2.f, frcp(1.f + fex2(SCALE_T * cn1)), -1.f);
    if (u0 + J < 50)
        *reinterpret_cast<ull*>(hbase + (u0 + J)*HSTR + rp2) = pack2(h0v, h1v);
}

__global__ void __launch_bounds__(NTH, 1)
lstm_v3_kernel(const float* __restrict__ x,
               const float* __restrict__ Wih0, const float* __restrict__ Whh0,
               const float* __restrict__ bih0, const float* __restrict__ bhh0,
               const float* __restrict__ Wih1, const float* __restrict__ Whh1,
               const float* __restrict__ bih1, const float* __restrict__ bhh1,
               const float* __restrict__ fcw_g, const float* __restrict__ fcb_g,
               float* __restrict__ out)
{
    extern __shared__ float sm[];
    float* wt1 = sm + OFF_WT1;
    float* wt0 = sm + OFF_WT0;
    float* wx0 = sm + OFF_WX0;
    float* bs0 = sm + OFF_B0;
    float* bs1 = sm + OFF_B1;
    float* hb0 = sm + OFF_HB0;
    float* hb1 = sm + OFF_HB1;
    float* fcs = sm + OFF_FC;

    const int tid = threadIdx.x;
    const int b0  = blockIdx.x * NB;

    // ---------------- staging (prescaled, transposed, padded) ----------------
    for (int idx = tid; idx < 100*GC; idx += NTH) {
        int k = idx >> 8, col = idx & 255;
        int u = col >> 2, g = col & 3;
        float s = (g == 2) ? SCALE_T : SCALE_S;
        float v = 0.f;
        if (u < 50) {
            int row = g*50 + u;
            v = (k < 50) ? Wih1[row*50 + k] : Whh1[row*50 + (k - 50)];
        }
        wt1[idx] = v * s;
    }
    for (int idx = tid; idx < 50*GC; idx += NTH) {
        int k = idx >> 8, col = idx & 255;
        int u = col >> 2, g = col & 3;
        float s = (g == 2) ? SCALE_T : SCALE_S;
        wt0[idx] = (u < 50) ? Whh0[(g*50 + u)*50 + k] * s : 0.f;
    }
    if (tid < GC) {
        int u = tid >> 2, g = tid & 3;
        float s = (g == 2) ? SCALE_T : SCALE_S;
        int row = g*50 + u;
        wx0[tid] = (u < 50) ? Wih0[row] * s : 0.f;
        bs0[tid] = (u < 50) ? (bih0[row] + bhh0[row]) * s : 0.f;
        bs1[tid] = (u < 50) ? (bih1[row] + bhh1[row]) * s : 0.f;
    }
    if (tid < 50) fcs[tid] = fcw_g[tid];
    for (int idx = tid; idx < 50*HSTR; idx += NTH) { hb0[idx] = 0.f; hb1[idx] = 0.f; }
    __syncthreads();

    // ---------------- per-thread geometry ----------------
    const int rp  = tid & 15;            // row-pair 0..15 (rows 2rp, 2rp+1)
    const int c   = tid >> 4;            // chunk 0..15 (16 cols = 4 units)
    const int rp2 = 2 * rp;
    const int co  = 16 * c;              // column offset
    const int u0  = 4 * c;               // first unit of chunk
    const bool worker = (c < 14);        // chunks 14,15 are pure padding (warp 7 idles)

    const float* wt1c = wt1 + co;
    const float* wt0c = wt0 + co;
    const float* wx0c = wx0 + co;
    const float* b0c  = bs0 + co;
    const float* b1c  = bs1 + co;
    const float* xrow = x + (size_t)(b0 + rp2) * T_LEN;   // rows rp2 (and +T_LEN for rp2+1)

    float c0s[8], c1s[8];                // c-state [2 rows][4 units] per layer
    #pragma unroll
    for (int j = 0; j < 8; ++j) { c0s[j] = 0.f; c1s[j] = 0.f; }

    ull g1[16];                          // saved L1 gate sums from previous t
    float xv0 = 0.f, xv1 = 0.f;          // x(t+1) for rows rp2, rp2+1

    // ---------------- prologue: h0(0) from x(0) + bias ----------------
    if (worker) {
        ull acc[16];
        initb16(acc, b0c);
        float p0 = xrow[0], p1 = xrow[T_LEN];
        mvk2(acc, pack2(p0, p0), pack2(p1, p1), wx0c);
        act_unit<0>(acc, c0s, hb0, u0, rp2);
        act_unit<1>(acc, c0s, hb0, u0, rp2);
        act_unit<2>(acc, c0s, hb0, u0, rp2);
        act_unit<3>(acc, c0s, hb0, u0, rp2);
        xv0 = xrow[1]; xv1 = xrow[T_LEN + 1];          // x(1) for body(0)
    }
    __syncthreads();

    // ---------------- main loop ----------------
    // body(t): h0(t)-matvec feeds acc1 (L1(t)) + acc0 (L0(t+1)); act1(t-1) interleaved.
    //          BAR. h1(t-1)-matvec finishes acc1; act0 -> h0(t+1) interleaved. save g1. BAR.
    for (int t = 0; t < T_LEN; ++t) {
        ull acc0[16], acc1[16];
        float xn0 = 0.f, xn1 = 0.f;
        if (worker) {
            initb16(acc1, b1c);
            initb16(acc0, b0c);
            mvk2(acc0, pack2(xv0, xv0), pack2(xv1, xv1), wx0c);  // x(t+1) rank-1
            int tn = (t + 2 < T_LEN) ? t + 2 : T_LEN - 1;        // prefetch x(t+2)
            xn0 = xrow[tn]; xn1 = xrow[T_LEN + tn];

            // -- h0(t) phase: 4 sub-ranges with act1(t-1) slices interleaved --
            #pragma unroll 2
            for (int k = 0; k < 13; ++k) {
                ull ha, hb; hsplat(hb0 + k*HSTR + rp2, ha, hb);
                mvk2(acc1, ha, hb, wt1c + k*GC);
                mvk2(acc0, ha, hb, wt0c + k*GC);
            }
            if (t > 0) act_unit<0>(g1, c1s, hb1, u0, rp2);
            #pragma unroll 2
            for (int k = 13; k < 26; ++k) {
                ull ha, hb; hsplat(hb0 + k*HSTR + rp2, ha, hb);
                mvk2(acc1, ha, hb, wt1c + k*GC);
                mvk2(acc0, ha, hb, wt0c + k*GC);
            }
            if (t > 0) act_unit<1>(g1, c1s, hb1, u0, rp2);
            #pragma unroll 2
            for (int k = 26; k < 39; ++k) {
                ull ha, hb; hsplat(hb0 + k*HSTR + rp2, ha, hb);
                mvk2(acc1, ha, hb, wt1c + k*GC);
                mvk2(acc0, ha, hb, wt0c + k*GC);
            }
            if (t > 0) act_unit<2>(g1, c1s, hb1, u0, rp2);
            #pragma unroll 2
            for (int k = 39; k < 50; ++k) {
                ull ha, hb; hsplat(hb0 + k*HSTR + rp2, ha, hb);
                mvk2(acc1, ha, hb, wt1c + k*GC);
                mvk2(acc0, ha, hb, wt0c + k*GC);
            }
            if (t > 0) act_unit<3>(g1, c1s, hb1, u0, rp2);
        }
        __syncthreads();   // h1(t-1) stores visible; h0(t) reads done before h0(t+1) writes

        if (worker) {
            // -- h1(t-1) phase: finish acc1; act0 -> h0(t+1) interleaved --
            #pragma unroll 2
            for (int k = 0; k < 13; ++k) {
                ull ha, hb; hsplat(hb1 + k*HSTR + rp2, ha, hb);
                mvk2(acc1, ha, hb, wt1c + (50 + k)*GC);
            }
            act_unit<0>(acc0, c0s, hb0, u0, rp2);
            #pragma unroll 2
            for (int k = 13; k < 26; ++k) {
                ull ha, hb; hsplat(hb1 + k*HSTR + rp2, ha, hb);
                mvk2(acc1, ha, hb, wt1c + (50 + k)*GC);
            }
            act_unit<1>(acc0, c0s, hb0, u0, rp2);
            #pragma unroll 2
            for (int k = 26; k < 39; ++k) {
                ull ha, hb; hsplat(hb1 + k*HSTR + rp2, ha, hb);
                mvk2(acc1, ha, hb, wt1c + (50 + k)*GC);
            }
            act_unit<2>(acc0, c0s, hb0, u0, rp2);
            #pragma unroll 2
            for (int k = 39; k < 50; ++k) {
                ull ha, hb; hsplat(hb1 + k*HSTR + rp2, ha, hb);
                mvk2(acc1, ha, hb, wt1c + (50 + k)*GC);
            }
            act_unit<3>(acc0, c0s, hb0, u0, rp2);

            #pragma unroll
            for (int i = 0; i < 16; ++i) g1[i] = acc1[i];  // defer act1 to next body
            xv0 = xn0; xv1 = xn1;
        }
        __syncthreads();   // h0(t+1) stores visible before next h0-phase reads
    }

    // ---------------- epilogue: act1(511) then FC ----------------
    if (worker) {
        act_unit<0>(g1, c1s, hb1, u0, rp2);
        act_unit<1>(g1, c1s, hb1, u0, rp2);
        act_unit<2>(g1, c1s, hb1, u0, rp2);
        act_unit<3>(g1, c1s, hb1, u0, rp2);
    }
    __syncthreads();

    if (tid < NB) {
        float s = fcb_g[0];
        #pragma unroll
        for (int u = 0; u < 50; ++u)
            s += fcs[u] * hb1[u*HSTR + tid];
        out[b0 + tid] = s;
    }
}

extern "C" void kernel_launch(void* const* d_in, const int* in_sizes, int n_in,
                              void* d_out, int out_size)
{
    const float* x    = (const float*)d_in[0];
    const float* Wih0 = (const float*)d_in[1];
    const float* Whh0 = (const float*)d_in[2];
    const float* bih0 = (const float*)d_in[3];
    const float* bhh0 = (const float*)d_in[4];
    const float* Wih1 = (const float*)d_in[5];
    const float* Whh1 = (const float*)d_in[6];
    const float* bih1 = (const float*)d_in[7];
    const float* bhh1 = (const float*)d_in[8];
    const float* fcw  = (const float*)d_in[9];
    const float* fcb  = (const float*)d_in[10];
    float* out = (float*)d_out;

    const int B = in_sizes[0] / T_LEN;            // 4096
    const int grid = B / NB;                      // 128 CTAs
    const size_t smem = SMEMF * sizeof(float);    // ~170 KB

    cudaFuncSetAttribute(lstm_v3_kernel,
                         cudaFuncAttributeMaxDynamicSharedMemorySize, (int)smem);

    lstm_v3_kernel<<<grid, NTH, smem>>>(
        x, Wih0, Whh0, bih0, bhh0, Wih1, Whh1, bih1, bhh1, fcw, fcb, out);
}